// round 10
// baseline (speedup 1.0000x reference)
#include <cuda_runtime.h>
#include <cuda_bf16.h>
#include <cstdint>
#include <cmath>

// Problem dims (fixed by the reference).
#define TT 512
#define BB 256
#define HH 512
#define G3 1536
#define MTOT (TT*BB)   // 131072

// -------------------- device scratch (no cudaMalloc allowed) --------------------
__device__ float    g_Xg[(size_t)MTOT * G3];        // fp32 input-side preactivations
__device__ uint16_t g_Xh[(size_t)MTOT * HH];        // bf16 hi of ins
__device__ uint16_t g_Xl[(size_t)MTOT * HH];        // bf16 lo of ins
__device__ uint16_t g_Wt_hi[(size_t)G3 * HH];       // input weights, transposed [ncol][k]
__device__ uint16_t g_Wt_lo[(size_t)G3 * HH];
__device__ uint16_t g_Wht_hi[(size_t)G3 * HH];      // hidden weights, transposed [ncol][k]
__device__ uint16_t g_Wht_lo[(size_t)G3 * HH];
__device__ uint16_t g_Hh[2 * BB * HH];              // ping-pong split h (hi)
__device__ uint16_t g_Hl[2 * BB * HH];              // ping-pong split h (lo)
__device__ float    g_bias[G3];
__device__ unsigned int g_bar;                      // persistent-kernel grid barrier

// -------------------- helpers --------------------
__device__ __forceinline__ uint32_t smem_u32(const void* p) {
    uint32_t a;
    asm("{ .reg .u64 t; cvta.to.shared.u64 t, %1; cvt.u32.u64 %0, t; }" : "=r"(a) : "l"(p));
    return a;
}
__device__ __forceinline__ void ldm_x4(uint32_t* r, uint32_t addr) {
    asm volatile("ldmatrix.sync.aligned.m8n8.x4.shared.b16 {%0,%1,%2,%3}, [%4];"
                 : "=r"(r[0]), "=r"(r[1]), "=r"(r[2]), "=r"(r[3]) : "r"(addr));
}
__device__ __forceinline__ void ldm_x2(uint32_t* r, uint32_t addr) {
    asm volatile("ldmatrix.sync.aligned.m8n8.x2.shared.b16 {%0,%1}, [%2];"
                 : "=r"(r[0]), "=r"(r[1]) : "r"(addr));
}
// D(16x8,f32) += A(16x16 bf16 row) * B(16x8 bf16 col)
__device__ __forceinline__ void mma16816(float* c, const uint32_t* a, const uint32_t* b) {
    asm volatile("mma.sync.aligned.m16n8k16.row.col.f32.bf16.bf16.f32 "
                 "{%0,%1,%2,%3}, {%4,%5,%6,%7}, {%8,%9}, {%0,%1,%2,%3};"
                 : "+f"(c[0]), "+f"(c[1]), "+f"(c[2]), "+f"(c[3])
                 : "r"(a[0]), "r"(a[1]), "r"(a[2]), "r"(a[3]), "r"(b[0]), "r"(b[1]));
}
__device__ __forceinline__ void cp16(uint32_t dst, const void* src) {
    asm volatile("cp.async.cg.shared.global [%0], [%1], 16;" :: "r"(dst), "l"(src));
}
__device__ __forceinline__ void cp16z(uint32_t dst, const void* src, uint32_t srcsz) {
    asm volatile("cp.async.cg.shared.global [%0], [%1], 16, %2;" :: "r"(dst), "l"(src), "r"(srcsz));
}
#define CP_COMMIT() asm volatile("cp.async.commit_group;" ::: "memory")
#define CP_WAIT0()  asm volatile("cp.async.wait_group 0;" ::: "memory")
__device__ __forceinline__ void split2(float x, uint16_t& h, uint16_t& l) {
    __nv_bfloat16 hb = __float2bfloat16_rn(x);
    __nv_bfloat16 lb = __float2bfloat16_rn(x - __bfloat162float(hb));
    h = __bfloat16_as_ushort(hb);
    l = __bfloat16_as_ushort(lb);
}
__device__ __forceinline__ float sigmoidf_(float x) { return 1.0f / (1.0f + expf(-x)); }

// ----------------------------------------------------------------------------
// Prep 1: split ins fp32 -> bf16 hi/lo, row-major [MTOT][512].
// ----------------------------------------------------------------------------
__global__ __launch_bounds__(256) void prep_x_kernel(const float* __restrict__ X) {
    size_t u = (size_t)blockIdx.x * 256 + threadIdx.x;
    if (u >= (size_t)MTOT * HH / 8) return;
    size_t base = u * 8;
    float4 v0 = *(const float4*)(X + base);
    float4 v1 = *(const float4*)(X + base + 4);
    float xs[8] = {v0.x, v0.y, v0.z, v0.w, v1.x, v1.y, v1.z, v1.w};
    uint16_t hp[8], lp[8];
#pragma unroll
    for (int j = 0; j < 8; ++j) split2(xs[j], hp[j], lp[j]);
    *(uint4*)(g_Xh + base) = *(uint4*)hp;
    *(uint4*)(g_Xl + base) = *(uint4*)lp;
}

// ----------------------------------------------------------------------------
// Prep 2: transpose + split BOTH weight sets: Wt[ncol][k] = W_gate[k][j].
// ----------------------------------------------------------------------------
__global__ __launch_bounds__(256) void prep_w_kernel(
    const float* __restrict__ Wir, const float* __restrict__ Wiz, const float* __restrict__ Win,
    const float* __restrict__ Whr, const float* __restrict__ Whz, const float* __restrict__ Whn,
    const float* __restrict__ bir, const float* __restrict__ biz, const float* __restrict__ bin) {
    int u = blockIdx.x * 256 + threadIdx.x;
    if (u >= G3 * HH / 8) return;
    int ncol = u >> 6;
    int k0 = (u & 63) * 8;
    int gate = ncol >> 9, j = ncol & 511;
    const float* Wi = (gate == 0) ? Wir : (gate == 1) ? Wiz : Win;
    const float* Wh = (gate == 0) ? Whr : (gate == 1) ? Whz : Whn;
    uint16_t ih[8], il[8], hh[8], hl[8];
#pragma unroll
    for (int i = 0; i < 8; ++i) {
        split2(Wi[(size_t)(k0 + i) * HH + j], ih[i], il[i]);
        split2(Wh[(size_t)(k0 + i) * HH + j], hh[i], hl[i]);
    }
    size_t off = (size_t)ncol * HH + k0;
    *(uint4*)(g_Wt_hi + off)  = *(uint4*)ih;
    *(uint4*)(g_Wt_lo + off)  = *(uint4*)il;
    *(uint4*)(g_Wht_hi + off) = *(uint4*)hh;
    *(uint4*)(g_Wht_lo + off) = *(uint4*)hl;
    if ((u & 63) == 0) {
        const float* bias = (gate == 0) ? bir : (gate == 1) ? biz : bin;
        g_bias[ncol] = bias[j];
    }
}

// ----------------------------------------------------------------------------
// Prep 3: split init_h into ping-pong buffer 0 (bf16 hi/lo); reset barrier.
// ----------------------------------------------------------------------------
__global__ __launch_bounds__(256) void prep_h_kernel(const float* __restrict__ H0) {
    int u = blockIdx.x * 256 + threadIdx.x;
    if (u == 0) g_bar = 0;
    if (u >= BB * HH / 8) return;
    size_t base = (size_t)u * 8;
    float4 v0 = *(const float4*)(H0 + base);
    float4 v1 = *(const float4*)(H0 + base + 4);
    float xs[8] = {v0.x, v0.y, v0.z, v0.w, v1.x, v1.y, v1.z, v1.w};
    uint16_t hp[8], lp[8];
#pragma unroll
    for (int j = 0; j < 8; ++j) split2(xs[j], hp[j], lp[j]);
    *(uint4*)(g_Hh + base) = *(uint4*)hp;
    *(uint4*)(g_Hl + base) = *(uint4*)lp;
}

// ----------------------------------------------------------------------------
// Input GEMM via mma.sync (tiling/math identical to R9 — proven). Staging now
// via cp.async (no LDG->reg->STS chain, -32 regs). 512 thr, 16 warps 4m x 4n,
// K-chunk 64, double-buffered. Grid (12 n fastest for L2 A-reuse, 1024 m).
// ----------------------------------------------------------------------------
#define IG_STRIDE 72
#define IG_BUF (128*IG_STRIDE)                 // elems per operand buffer
#define IG_SMEM_BYTES (8 * IG_BUF * 2)         // 147456

__global__ __launch_bounds__(512, 1) void input_gemm_mma() {
    extern __shared__ __align__(16) uint16_t ig_sm[];
    const uint32_t smb = smem_u32(ig_sm);
    const int tid = threadIdx.x;
    const int w = tid >> 5, l = tid & 31;
    const int n0 = blockIdx.x * 128;    // n fastest for L2 A-reuse
    const int m0 = blockIdx.y * 128;
    const int wm = w >> 2, wn = w & 3;  // 4m x 4n, warp tile 32x32

    float c[2][4][4];
#pragma unroll
    for (int mi = 0; mi < 2; ++mi)
#pragma unroll
        for (int ni = 0; ni < 4; ++ni)
#pragma unroll
            for (int q = 0; q < 4; ++q) c[mi][ni][q] = 0.0f;

    const int ar = tid >> 2, seg = tid & 3;   // 128 rows, 4 thr/row (16 k each)
    const uint32_t stoff = (uint32_t)(ar * IG_STRIDE + seg * 16) * 2;   // bytes

    // Buffer byte bases: stage s: Ah = s*4*IG_BUF*2 + 0, Al +1, Bh +2, Bl +3 (in IG_BUF*2 units)
#define IG_ISSUE(cb) {                                                                  \
    const int kt = (cb) * 64;                                                           \
    const uint32_t bb = smb + (uint32_t)((cb) & 1) * (4u * IG_BUF * 2u);                \
    const uint16_t* pah = g_Xh + (size_t)(m0 + ar) * HH + kt + seg * 16;                \
    const uint16_t* pal = g_Xl + (size_t)(m0 + ar) * HH + kt + seg * 16;                \
    const uint16_t* pbh = g_Wt_hi + (size_t)(n0 + ar) * HH + kt + seg * 16;             \
    const uint16_t* pbl = g_Wt_lo + (size_t)(n0 + ar) * HH + kt + seg * 16;             \
    cp16(bb + 0u * IG_BUF * 2u + stoff,      pah);                                      \
    cp16(bb + 0u * IG_BUF * 2u + stoff + 16, pah + 8);                                  \
    cp16(bb + 1u * IG_BUF * 2u + stoff,      pal);                                      \
    cp16(bb + 1u * IG_BUF * 2u + stoff + 16, pal + 8);                                  \
    cp16(bb + 2u * IG_BUF * 2u + stoff,      pbh);                                      \
    cp16(bb + 2u * IG_BUF * 2u + stoff + 16, pbh + 8);                                  \
    cp16(bb + 3u * IG_BUF * 2u + stoff,      pbl);                                      \
    cp16(bb + 3u * IG_BUF * 2u + stoff + 16, pbl + 8);                                  \
    CP_COMMIT(); }

    IG_ISSUE(0);
    for (int cb = 0; cb < 8; ++cb) {
        CP_WAIT0();
        __syncthreads();
        if (cb < 7) IG_ISSUE(cb + 1);

        const uint16_t* Ah = ig_sm + (size_t)(cb & 1) * 4 * IG_BUF + 0 * IG_BUF;
        const uint16_t* Al = ig_sm + (size_t)(cb & 1) * 4 * IG_BUF + 1 * IG_BUF;
        const uint16_t* Bh = ig_sm + (size_t)(cb & 1) * 4 * IG_BUF + 2 * IG_BUF;
        const uint16_t* Bl = ig_sm + (size_t)(cb & 1) * 4 * IG_BUF + 3 * IG_BUF;

#pragma unroll
        for (int kc = 0; kc < 64; kc += 16) {
            uint32_t bfh[4][2], bfl[4][2];
#pragma unroll
            for (int ni = 0; ni < 4; ++ni) {
                const int nrow = wn * 32 + ni * 8 + (l & 7);
                const int ncolk = kc + ((l >> 3) & 1) * 8;
                ldm_x2(bfh[ni], smem_u32(&Bh[nrow * IG_STRIDE + ncolk]));
                ldm_x2(bfl[ni], smem_u32(&Bl[nrow * IG_STRIDE + ncolk]));
            }
#pragma unroll
            for (int mi = 0; mi < 2; ++mi) {
                uint32_t afh[4], afl[4];
                const int row = wm * 32 + mi * 16 + (l & 15);
                const int col = kc + (l >> 4) * 8;
                ldm_x4(afh, smem_u32(&Ah[row * IG_STRIDE + col]));
                ldm_x4(afl, smem_u32(&Al[row * IG_STRIDE + col]));
#pragma unroll
                for (int ni = 0; ni < 4; ++ni) {
                    mma16816(c[mi][ni], afh, bfh[ni]);
                    mma16816(c[mi][ni], afh, bfl[ni]);
                    mma16816(c[mi][ni], afl, bfh[ni]);
                }
            }
        }
        // need all warps done reading this stage before its buffer is re-issued
        __syncthreads();
    }
#undef IG_ISSUE

    const int g = l >> 2, tq = l & 3;
#pragma unroll
    for (int mi = 0; mi < 2; ++mi)
#pragma unroll
        for (int ni = 0; ni < 4; ++ni) {
            const int ncol = n0 + wn * 32 + ni * 8 + tq * 2;
            const float2 bv = *(const float2*)&g_bias[ncol];
            const int row = m0 + wm * 32 + mi * 16 + g;
            float2 v0 = {c[mi][ni][0] + bv.x, c[mi][ni][1] + bv.y};
            float2 v1 = {c[mi][ni][2] + bv.x, c[mi][ni][3] + bv.y};
            *(float2*)&g_Xg[(size_t)row * G3 + ncol]       = v0;
            *(float2*)&g_Xg[(size_t)(row + 8) * G3 + ncol] = v1;
        }
}

// ----------------------------------------------------------------------------
// Persistent GRU recurrence, redistributed: grid (32 j-tiles x 4 b-quarters)
// = 128 CTAs, 512 thr = 16 warps (4 m x 4 k-quarters).
//  - h-broadcast traffic halved (16 j-cols/CTA, 64 b-rows/CTA)
//  - A and W in blocked no-pad smem layouts (A 128KB + W 96KB = 224KB)
//  - per-quarter cp.async staging (zero-fill src_size = reset mask) + named
//    barrier per quarter: NO full-CTA sync in the mainloop
//  - 4-way k-reduction through reused A smem; epilogue in wk==0 warps with
//    register h-carry; Xg[t+1] prefetched before the grid barrier.
// ----------------------------------------------------------------------------
#define SKB_AH 0
#define SKB_AL 65536
#define SKB_WH 131072
#define SKB_WL 180224
#define SKB_TOTAL 229376

__global__ __launch_bounds__(512) void gru_persistent(
    const int* __restrict__ resets, const float* __restrict__ init_h,
    const float* __restrict__ bhn, float* __restrict__ out)
{
    extern __shared__ __align__(16) char sk_sm[];
    const uint32_t smb = smem_u32(sk_sm);
    float* red_buf = (float*)sk_sm;                 // reuses A region between syncs

    const int tid = threadIdx.x;
    const int w = tid >> 5, l = tid & 31;
    const int wm = w & 3, wk = w >> 2;              // m-warp 0..3, k-quarter 0..3
    const int j0 = blockIdx.x * 16;                 // 16 j-cols per gate
    const int b0 = blockIdx.y * 64;                 // 64 batch rows
    const int g = l >> 2, tq = l & 3;

    // Load W slices once: rows = gate*16 + jj (48), k 0..511, blocked [k/16][48][16].
    for (int u = tid; u < 48 * 64; u += 512) {
        const int row = u >> 6, q = u & 63;
        const int gate = row >> 4;
        const int ncol = gate * 512 + j0 + (row & 15);
        const int k = q * 8;
        const uint32_t doff = (uint32_t)(((k >> 4) * 48 + row) * 32 + (k & 15) * 2);
        *(uint4*)(sk_sm + SKB_WH + doff) = *(const uint4*)(g_Wht_hi + (size_t)ncol * HH + k);
        *(uint4*)(sk_sm + SKB_WL + doff) = *(const uint4*)(g_Wht_lo + (size_t)ncol * HH + k);
    }
    __syncthreads();

    // Staging geometry: thread covers 1 k-block (16 k) x 4 rows in its quarter.
    const int quarter = tid >> 7;                   // == wk for MMA warps
    const int qlocal = tid & 127;
    const int sblk = quarter * 8 + (qlocal >> 4);   // k-block 0..31
    const int srow0 = (qlocal & 15) * 4;            // first of 4 rows

    // Epilogue state (wk==0 threads) + staging resets (all threads).
    float2 hc[2][2];        // h carry [rr][f]
    float2 pxG[3][2][2];    // Xg [gate][rr][f]
    bool rzrow[2];
    int rstage[4];
    float2 bh2[2];
    bh2[0] = *(const float2*)&bhn[j0 + 0 + tq * 2];
    bh2[1] = *(const float2*)&bhn[j0 + 8 + tq * 2];
    {
        const int* rst = resets;    // t = 0
#pragma unroll
        for (int r4 = 0; r4 < 4; ++r4) rstage[r4] = rst[b0 + srow0 + r4];
        if (wk == 0) {
#pragma unroll
            for (int rr = 0; rr < 2; ++rr) {
                const int row = b0 + wm * 16 + g + rr * 8;
                rzrow[rr] = rst[row] != 0;
#pragma unroll
                for (int f = 0; f < 2; ++f) {
                    const int jj = j0 + f * 8 + tq * 2;
                    hc[rr][f] = *(const float2*)&init_h[(size_t)row * HH + jj];
#pragma unroll
                    for (int gate = 0; gate < 3; ++gate)
                        pxG[gate][rr][f] = *(const float2*)&g_Xg[(size_t)row * G3 + gate * 512 + jj];
                }
            }
        }
    }

    for (int t = 0; t < TT; ++t) {
        const int par = t & 1;
        const uint16_t* Hh = g_Hh + (size_t)par * BB * HH;
        const uint16_t* Hl = g_Hl + (size_t)par * BB * HH;

        // --- stage own k-quarter via cp.async with in-flight reset masking ---
#pragma unroll
        for (int r4 = 0; r4 < 4; ++r4) {
            const int row = srow0 + r4;
            const uint32_t sz = rstage[r4] ? 0u : 16u;
            const uint32_t d = (uint32_t)(sblk * 2048 + row * 32);
            const uint16_t* sh = Hh + (size_t)(b0 + row) * HH + sblk * 16;
            const uint16_t* sl = Hl + (size_t)(b0 + row) * HH + sblk * 16;
            cp16z(smb + SKB_AH + d,      sh,     sz);
            cp16z(smb + SKB_AH + d + 16, sh + 8, sz);
            cp16z(smb + SKB_AL + d,      sl,     sz);
            cp16z(smb + SKB_AL + d + 16, sl + 8, sz);
        }
        CP_COMMIT();
        CP_WAIT0();
        asm volatile("bar.sync %0, 128;" :: "r"(quarter + 1) : "memory");

        // --- MMA on own k-quarter: warp (wm, wk), c[6 n-frags][4] ---
        float c[6][4];
#pragma unroll
        for (int ni = 0; ni < 6; ++ni)
#pragma unroll
            for (int q = 0; q < 4; ++q) c[ni][q] = 0.0f;

#pragma unroll
        for (int ki = 0; ki < 8; ++ki) {
            const int blk = wk * 8 + ki;
            uint32_t afh[4], afl[4];
            const uint32_t aoff = (uint32_t)(blk * 2048 + (wm * 16 + (l & 15)) * 32 + (l >> 4) * 16);
            ldm_x4(afh, smb + SKB_AH + aoff);
            ldm_x4(afl, smb + SKB_AL + aoff);
#pragma unroll
            for (int ni = 0; ni < 6; ++ni) {
                const uint32_t woff = (uint32_t)(blk * 1536 + (ni * 8 + (l & 7)) * 32 + ((l >> 3) & 1) * 16);
                uint32_t bfh[2], bfl[2];
                ldm_x2(bfh, smb + SKB_WH + woff);
                ldm_x2(bfl, smb + SKB_WL + woff);
                mma16816(c[ni], afh, bfh);
                mma16816(c[ni], afh, bfl);
                mma16816(c[ni], afl, bfh);
            }
        }
        __syncthreads();   // all MMA smem reads done; A region reusable

        // --- 4-way k reduction via smem (layout [24][384] floats, conflict-free) ---
        if (wk != 0) {
            float* dst = red_buf + (wk - 1) * 128 + wm * 32 + l;
#pragma unroll
            for (int ni = 0; ni < 6; ++ni)
#pragma unroll
                for (int q = 0; q < 4; ++q)
                    dst[(ni * 4 + q) * 384] = c[ni][q];
        }
        __syncthreads();

        if (wk == 0) {
            const float* src = red_buf + wm * 32 + l;
#pragma unroll
            for (int ni = 0; ni < 6; ++ni)
#pragma unroll
                for (int q = 0; q < 4; ++q) {
                    const float* s = src + (ni * 4 + q) * 384;
                    c[ni][q] += s[0] + s[128] + s[256];
                }

            // --- fused GRU epilogue, register h-carry ---
            float* outt = out + (size_t)t * BB * HH;
            uint16_t* nHh = g_Hh + (size_t)(par ^ 1) * BB * HH;
            uint16_t* nHl = g_Hl + (size_t)(par ^ 1) * BB * HH;
#pragma unroll
            for (int rr = 0; rr < 2; ++rr) {
                const int row = b0 + wm * 16 + g + rr * 8;
#pragma unroll
                for (int f = 0; f < 2; ++f) {
                    const int jj = j0 + f * 8 + tq * 2;
                    float2 hp = hc[rr][f];
                    if (rzrow[rr]) { hp.x = 0.0f; hp.y = 0.0f; }
                    const float r0 = sigmoidf_(pxG[0][rr][f].x + c[0 + f][rr * 2 + 0]);
                    const float r1 = sigmoidf_(pxG[0][rr][f].y + c[0 + f][rr * 2 + 1]);
                    const float z0 = sigmoidf_(pxG[1][rr][f].x + c[2 + f][rr * 2 + 0]);
                    const float z1 = sigmoidf_(pxG[1][rr][f].y + c[2 + f][rr * 2 + 1]);
                    const float n0 = tanhf(pxG[2][rr][f].x + r0 * (c[4 + f][rr * 2 + 0] + bh2[f].x));
                    const float n1 = tanhf(pxG[2][rr][f].y + r1 * (c[4 + f][rr * 2 + 1] + bh2[f].y));
                    const float h0 = (1.0f - z0) * n0 + z0 * hp.x;
                    const float h1 = (1.0f - z1) * n1 + z1 * hp.y;
                    *(float2*)&outt[(size_t)row * HH + jj] = make_float2(h0, h1);
                    hc[rr][f] = make_float2(h0, h1);
                    uint16_t hh0, hl0, hh1, hl1;
                    split2(h0, hh0, hl0);
                    split2(h1, hh1, hl1);
                    *(uint32_t*)&nHh[(size_t)row * HH + jj] = ((uint32_t)hh1 << 16) | hh0;
                    *(uint32_t*)&nHl[(size_t)row * HH + jj] = ((uint32_t)hl1 << 16) | hl0;
                }
            }
        }

        // --- prefetch t+1 operands independent of h (hidden by the barrier) ---
        if (t + 1 < TT) {
            const int* rstn = resets + (t + 1) * BB;
#pragma unroll
            for (int r4 = 0; r4 < 4; ++r4) rstage[r4] = rstn[b0 + srow0 + r4];
            if (wk == 0) {
                const float* xgb = g_Xg + (size_t)(t + 1) * BB * G3;
#pragma unroll
                for (int rr = 0; rr < 2; ++rr) {
                    const int row = b0 + wm * 16 + g + rr * 8;
                    rzrow[rr] = rstn[row] != 0;
#pragma unroll
                    for (int f = 0; f < 2; ++f) {
                        const int jj = j0 + f * 8 + tq * 2;
#pragma unroll
                        for (int gate = 0; gate < 3; ++gate)
                            pxG[gate][rr][f] = *(const float2*)&xgb[(size_t)row * G3 + gate * 512 + jj];
                    }
                }
            }
        }

        // --- grid barrier ---
        __threadfence();
        __syncthreads();
        if (tid == 0) {
            asm volatile("red.release.gpu.add.u32 [%0], %1;" :: "l"(&g_bar), "r"(1u) : "memory");
            const unsigned target = 128u * (unsigned)(t + 1);
            unsigned v;
            do {
                asm volatile("ld.acquire.gpu.u32 %0, [%1];" : "=r"(v) : "l"(&g_bar) : "memory");
                if (v >= target) break;
                __nanosleep(32);
            } while (true);
        }
        __syncthreads();
    }
}

// ----------------------------------------------------------------------------
// Launch: 3 prep kernels + mma input GEMM + ONE persistent recurrence kernel.
// Graph-capturable (kernel launches only), allocation-free.
// ----------------------------------------------------------------------------
extern "C" void kernel_launch(void* const* d_in, const int* in_sizes, int n_in,
                              void* d_out, int out_size)
{
    const float* ins    = (const float*)d_in[0];
    const int*   resets = (const int*)d_in[1];
    const float* init_h = (const float*)d_in[2];
    const float* W_ir   = (const float*)d_in[3];
    const float* W_iz   = (const float*)d_in[4];
    const float* W_in   = (const float*)d_in[5];
    const float* b_ir   = (const float*)d_in[6];
    const float* b_iz   = (const float*)d_in[7];
    const float* b_in   = (const float*)d_in[8];
    const float* W_hr   = (const float*)d_in[9];
    const float* W_hz   = (const float*)d_in[10];
    const float* W_hn   = (const float*)d_in[11];
    const float* b_hn   = (const float*)d_in[12];
    float* out = (float*)d_out;

    cudaFuncSetAttribute(input_gemm_mma,
                         cudaFuncAttributeMaxDynamicSharedMemorySize, IG_SMEM_BYTES);
    cudaFuncSetAttribute(gru_persistent,
                         cudaFuncAttributeMaxDynamicSharedMemorySize, SKB_TOTAL);

    prep_x_kernel<<<(int)(((size_t)MTOT * HH / 8 + 255) / 256), 256>>>(ins);
    prep_w_kernel<<<(G3 * HH / 8 + 255) / 256, 256>>>(W_ir, W_iz, W_in,
                                                      W_hr, W_hz, W_hn,
                                                      b_ir, b_iz, b_in);
    prep_h_kernel<<<(BB * HH / 8 + 255) / 256, 256>>>(init_h);

    input_gemm_mma<<<dim3(G3 / 128, MTOT / 128), 512, IG_SMEM_BYTES>>>();

    gru_persistent<<<dim3(32, 4), 512, SKB_TOTAL>>>(resets, init_h, b_hn, out);
}

// round 11
// speedup vs baseline: 1.0267x; 1.0267x over previous
#include <cuda_runtime.h>
#include <cuda_bf16.h>
#include <cstdint>
#include <cmath>

// Problem dims (fixed by the reference).
#define TT 512
#define BB 256
#define HH 512
#define G3 1536
#define MTOT (TT*BB)   // 131072

// -------------------- device scratch (no cudaMalloc allowed) --------------------
__device__ float    g_Xg[(size_t)MTOT * G3];        // fp32 input-side preactivations
__device__ uint16_t g_Xh[(size_t)MTOT * HH];        // bf16 hi of ins
__device__ uint16_t g_Xl[(size_t)MTOT * HH];        // bf16 lo of ins
__device__ uint16_t g_Wt_hi[(size_t)G3 * HH];       // input weights, transposed [ncol][k]
__device__ uint16_t g_Wt_lo[(size_t)G3 * HH];
__device__ uint16_t g_Wht_hi[(size_t)G3 * HH];      // hidden weights, transposed [ncol][k]
__device__ uint16_t g_Wht_lo[(size_t)G3 * HH];
__device__ uint16_t g_Hh[2 * BB * HH];              // ping-pong split h (hi)
__device__ uint16_t g_Hl[2 * BB * HH];              // ping-pong split h (lo)
__device__ float    g_bias[G3];
__device__ unsigned int g_bar4[4];                  // per-b-quarter barriers (32 CTAs each)

// -------------------- helpers --------------------
__device__ __forceinline__ uint32_t smem_u32(const void* p) {
    uint32_t a;
    asm("{ .reg .u64 t; cvta.to.shared.u64 t, %1; cvt.u32.u64 %0, t; }" : "=r"(a) : "l"(p));
    return a;
}
__device__ __forceinline__ void ldm_x4(uint32_t* r, uint32_t addr) {
    asm volatile("ldmatrix.sync.aligned.m8n8.x4.shared.b16 {%0,%1,%2,%3}, [%4];"
                 : "=r"(r[0]), "=r"(r[1]), "=r"(r[2]), "=r"(r[3]) : "r"(addr));
}
__device__ __forceinline__ void ldm_x2(uint32_t* r, uint32_t addr) {
    asm volatile("ldmatrix.sync.aligned.m8n8.x2.shared.b16 {%0,%1}, [%2];"
                 : "=r"(r[0]), "=r"(r[1]) : "r"(addr));
}
// D(16x8,f32) += A(16x16 bf16 row) * B(16x8 bf16 col)
__device__ __forceinline__ void mma16816(float* c, const uint32_t* a, const uint32_t* b) {
    asm volatile("mma.sync.aligned.m16n8k16.row.col.f32.bf16.bf16.f32 "
                 "{%0,%1,%2,%3}, {%4,%5,%6,%7}, {%8,%9}, {%0,%1,%2,%3};"
                 : "+f"(c[0]), "+f"(c[1]), "+f"(c[2]), "+f"(c[3])
                 : "r"(a[0]), "r"(a[1]), "r"(a[2]), "r"(a[3]), "r"(b[0]), "r"(b[1]));
}
__device__ __forceinline__ void cp16z(uint32_t dst, const void* src, uint32_t srcsz) {
    asm volatile("cp.async.cg.shared.global [%0], [%1], 16, %2;" :: "r"(dst), "l"(src), "r"(srcsz));
}
#define CP_COMMIT() asm volatile("cp.async.commit_group;" ::: "memory")
#define CP_WAIT0()  asm volatile("cp.async.wait_group 0;" ::: "memory")
__device__ __forceinline__ void split2(float x, uint16_t& h, uint16_t& l) {
    __nv_bfloat16 hb = __float2bfloat16_rn(x);
    __nv_bfloat16 lb = __float2bfloat16_rn(x - __bfloat162float(hb));
    h = __bfloat16_as_ushort(hb);
    l = __bfloat16_as_ushort(lb);
}
__device__ __forceinline__ float sigmoidf_(float x) { return 1.0f / (1.0f + expf(-x)); }

// ----------------------------------------------------------------------------
// Prep 1: split ins fp32 -> bf16 hi/lo, row-major [MTOT][512].
// ----------------------------------------------------------------------------
__global__ __launch_bounds__(256) void prep_x_kernel(const float* __restrict__ X) {
    size_t u = (size_t)blockIdx.x * 256 + threadIdx.x;
    if (u >= (size_t)MTOT * HH / 8) return;
    size_t base = u * 8;
    float4 v0 = *(const float4*)(X + base);
    float4 v1 = *(const float4*)(X + base + 4);
    float xs[8] = {v0.x, v0.y, v0.z, v0.w, v1.x, v1.y, v1.z, v1.w};
    uint16_t hp[8], lp[8];
#pragma unroll
    for (int j = 0; j < 8; ++j) split2(xs[j], hp[j], lp[j]);
    *(uint4*)(g_Xh + base) = *(uint4*)hp;
    *(uint4*)(g_Xl + base) = *(uint4*)lp;
}

// ----------------------------------------------------------------------------
// Prep 2: transpose + split BOTH weight sets: Wt[ncol][k] = W_gate[k][j].
// ----------------------------------------------------------------------------
__global__ __launch_bounds__(256) void prep_w_kernel(
    const float* __restrict__ Wir, const float* __restrict__ Wiz, const float* __restrict__ Win,
    const float* __restrict__ Whr, const float* __restrict__ Whz, const float* __restrict__ Whn,
    const float* __restrict__ bir, const float* __restrict__ biz, const float* __restrict__ bin) {
    int u = blockIdx.x * 256 + threadIdx.x;
    if (u >= G3 * HH / 8) return;
    int ncol = u >> 6;
    int k0 = (u & 63) * 8;
    int gate = ncol >> 9, j = ncol & 511;
    const float* Wi = (gate == 0) ? Wir : (gate == 1) ? Wiz : Win;
    const float* Wh = (gate == 0) ? Whr : (gate == 1) ? Whz : Whn;
    uint16_t ih[8], il[8], hh[8], hl[8];
#pragma unroll
    for (int i = 0; i < 8; ++i) {
        split2(Wi[(size_t)(k0 + i) * HH + j], ih[i], il[i]);
        split2(Wh[(size_t)(k0 + i) * HH + j], hh[i], hl[i]);
    }
    size_t off = (size_t)ncol * HH + k0;
    *(uint4*)(g_Wt_hi + off)  = *(uint4*)ih;
    *(uint4*)(g_Wt_lo + off)  = *(uint4*)il;
    *(uint4*)(g_Wht_hi + off) = *(uint4*)hh;
    *(uint4*)(g_Wht_lo + off) = *(uint4*)hl;
    if ((u & 63) == 0) {
        const float* bias = (gate == 0) ? bir : (gate == 1) ? biz : bin;
        g_bias[ncol] = bias[j];
    }
}

// ----------------------------------------------------------------------------
// Prep 3: split init_h into ping-pong buffer 0 (bf16 hi/lo); reset barriers.
// ----------------------------------------------------------------------------
__global__ __launch_bounds__(256) void prep_h_kernel(const float* __restrict__ H0) {
    int u = blockIdx.x * 256 + threadIdx.x;
    if (u < 4) g_bar4[u] = 0;
    if (u >= BB * HH / 8) return;
    size_t base = (size_t)u * 8;
    float4 v0 = *(const float4*)(H0 + base);
    float4 v1 = *(const float4*)(H0 + base + 4);
    float xs[8] = {v0.x, v0.y, v0.z, v0.w, v1.x, v1.y, v1.z, v1.w};
    uint16_t hp[8], lp[8];
#pragma unroll
    for (int j = 0; j < 8; ++j) split2(xs[j], hp[j], lp[j]);
    *(uint4*)(g_Hh + base) = *(uint4*)hp;
    *(uint4*)(g_Hl + base) = *(uint4*)lp;
}

// ----------------------------------------------------------------------------
// Input GEMM via mma.sync — EXACT R9 version (proven fastest: LDG->STS staging,
// ONE syncthreads per 64-k chunk). 512 thr, 16 warps 4m x 4n, double-buffered.
// Grid (12 n fastest for L2 A-reuse, 1024 m).
// ----------------------------------------------------------------------------
#define IG_STRIDE 72
#define IG_BUF (128*IG_STRIDE)
#define IG_SMEM_BYTES (8 * IG_BUF * 2)   // 147456

__global__ __launch_bounds__(512, 1) void input_gemm_mma() {
    extern __shared__ __align__(16) uint16_t ig_sm[];
    uint16_t* Abufh[2]; uint16_t* Abufl[2]; uint16_t* Bbufh[2]; uint16_t* Bbufl[2];
    {
        uint16_t* p = ig_sm;
        Abufh[0] = p; p += IG_BUF;  Abufl[0] = p; p += IG_BUF;
        Bbufh[0] = p; p += IG_BUF;  Bbufl[0] = p; p += IG_BUF;
        Abufh[1] = p; p += IG_BUF;  Abufl[1] = p; p += IG_BUF;
        Bbufh[1] = p; p += IG_BUF;  Bbufl[1] = p;
    }
    const int tid = threadIdx.x;
    const int w = tid >> 5, l = tid & 31;
    const int n0 = blockIdx.x * 128;    // n fastest for L2 A-reuse
    const int m0 = blockIdx.y * 128;
    const int wm = w >> 2, wn = w & 3;  // 4m x 4n, warp tile 32x32

    float c[2][4][4];
#pragma unroll
    for (int mi = 0; mi < 2; ++mi)
#pragma unroll
        for (int ni = 0; ni < 4; ++ni)
#pragma unroll
            for (int q = 0; q < 4; ++q) c[mi][ni][q] = 0.0f;

    const int ar = tid >> 2, seg = tid & 3;   // 128 rows, 4 thr/row (16 k each)

    uint4 sA[4], sB[4];
#define IG_LDG(kt) {                                                                   \
    const uint16_t* pah = g_Xh + (size_t)(m0 + ar) * HH + (kt) + seg * 16;             \
    const uint16_t* pal = g_Xl + (size_t)(m0 + ar) * HH + (kt) + seg * 16;             \
    sA[0] = *(const uint4*)pah;       sA[1] = *(const uint4*)(pah + 8);                \
    sA[2] = *(const uint4*)pal;       sA[3] = *(const uint4*)(pal + 8);                \
    const uint16_t* pbh = g_Wt_hi + (size_t)(n0 + ar) * HH + (kt) + seg * 16;          \
    const uint16_t* pbl = g_Wt_lo + (size_t)(n0 + ar) * HH + (kt) + seg * 16;          \
    sB[0] = *(const uint4*)pbh;       sB[1] = *(const uint4*)(pbh + 8);                \
    sB[2] = *(const uint4*)pbl;       sB[3] = *(const uint4*)(pbl + 8); }

    IG_LDG(0);
    for (int cb = 0; cb < 8; ++cb) {
        uint16_t* Ah = Abufh[cb & 1]; uint16_t* Al = Abufl[cb & 1];
        uint16_t* Bh = Bbufh[cb & 1]; uint16_t* Bl = Bbufl[cb & 1];
        *(uint4*)&Ah[ar * IG_STRIDE + seg * 16]     = sA[0];
        *(uint4*)&Ah[ar * IG_STRIDE + seg * 16 + 8] = sA[1];
        *(uint4*)&Al[ar * IG_STRIDE + seg * 16]     = sA[2];
        *(uint4*)&Al[ar * IG_STRIDE + seg * 16 + 8] = sA[3];
        *(uint4*)&Bh[ar * IG_STRIDE + seg * 16]     = sB[0];
        *(uint4*)&Bh[ar * IG_STRIDE + seg * 16 + 8] = sB[1];
        *(uint4*)&Bl[ar * IG_STRIDE + seg * 16]     = sB[2];
        *(uint4*)&Bl[ar * IG_STRIDE + seg * 16 + 8] = sB[3];
        __syncthreads();
        if (cb < 7) IG_LDG((cb + 1) * 64);

#pragma unroll
        for (int kc = 0; kc < 64; kc += 16) {
            uint32_t bfh[4][2], bfl[4][2];
#pragma unroll
            for (int ni = 0; ni < 4; ++ni) {
                const int nrow = wn * 32 + ni * 8 + (l & 7);
                const int ncolk = kc + ((l >> 3) & 1) * 8;
                ldm_x2(bfh[ni], smem_u32(&Bh[nrow * IG_STRIDE + ncolk]));
                ldm_x2(bfl[ni], smem_u32(&Bl[nrow * IG_STRIDE + ncolk]));
            }
#pragma unroll
            for (int mi = 0; mi < 2; ++mi) {
                uint32_t afh[4], afl[4];
                const int row = wm * 32 + mi * 16 + (l & 15);
                const int col = kc + (l >> 4) * 8;
                ldm_x4(afh, smem_u32(&Ah[row * IG_STRIDE + col]));
                ldm_x4(afl, smem_u32(&Al[row * IG_STRIDE + col]));
#pragma unroll
                for (int ni = 0; ni < 4; ++ni) {
                    mma16816(c[mi][ni], afh, bfh[ni]);
                    mma16816(c[mi][ni], afh, bfl[ni]);
                    mma16816(c[mi][ni], afl, bfh[ni]);
                }
            }
        }
        if (cb == 7) break;
    }
#undef IG_LDG

    const int g = l >> 2, tq = l & 3;
#pragma unroll
    for (int mi = 0; mi < 2; ++mi)
#pragma unroll
        for (int ni = 0; ni < 4; ++ni) {
            const int ncol = n0 + wn * 32 + ni * 8 + tq * 2;
            const float2 bv = *(const float2*)&g_bias[ncol];
            const int row = m0 + wm * 32 + mi * 16 + g;
            float2 v0 = {c[mi][ni][0] + bv.x, c[mi][ni][1] + bv.y};
            float2 v1 = {c[mi][ni][2] + bv.x, c[mi][ni][3] + bv.y};
            *(float2*)&g_Xg[(size_t)row * G3 + ncol]       = v0;
            *(float2*)&g_Xg[(size_t)(row + 8) * G3 + ncol] = v1;
        }
}

// ----------------------------------------------------------------------------
// Persistent GRU recurrence (R10 math, proven). CHANGE: per-b-quarter grid
// barrier — CTA (j,b) at step t+1 only reads h rows of its own b-quarter,
// written by the 32 CTAs sharing blockIdx.y. 4 independent 32-CTA barriers
// (g_bar4[b]) replace the single 128-CTA barrier: smaller straggler max,
// quarters drift independently and absorb jitter.
// Grid (32 j-tiles x 4 b-quarters) = 128 CTAs, 512 thr = 16 warps (4m x 4k).
// ----------------------------------------------------------------------------
#define SKB_AH 0
#define SKB_AL 65536
#define SKB_WH 131072
#define SKB_WL 180224
#define SKB_TOTAL 229376

__global__ __launch_bounds__(512) void gru_persistent(
    const int* __restrict__ resets, const float* __restrict__ init_h,
    const float* __restrict__ bhn, float* __restrict__ out)
{
    extern __shared__ __align__(16) char sk_sm[];
    const uint32_t smb = smem_u32(sk_sm);
    float* red_buf = (float*)sk_sm;                 // reuses A region between syncs

    const int tid = threadIdx.x;
    const int w = tid >> 5, l = tid & 31;
    const int wm = w & 3, wk = w >> 2;              // m-warp 0..3, k-quarter 0..3
    const int j0 = blockIdx.x * 16;                 // 16 j-cols per gate
    const int b0 = blockIdx.y * 64;                 // 64 batch rows
    const int g = l >> 2, tq = l & 3;
    unsigned int* const my_bar = &g_bar4[blockIdx.y];

    // Load W slices once: rows = gate*16 + jj (48), k 0..511, blocked [k/16][48][16].
    for (int u = tid; u < 48 * 64; u += 512) {
        const int row = u >> 6, q = u & 63;
        const int gate = row >> 4;
        const int ncol = gate * 512 + j0 + (row & 15);
        const int k = q * 8;
        const uint32_t doff = (uint32_t)(((k >> 4) * 48 + row) * 32 + (k & 15) * 2);
        *(uint4*)(sk_sm + SKB_WH + doff) = *(const uint4*)(g_Wht_hi + (size_t)ncol * HH + k);
        *(uint4*)(sk_sm + SKB_WL + doff) = *(const uint4*)(g_Wht_lo + (size_t)ncol * HH + k);
    }
    __syncthreads();

    // Staging geometry: thread covers 1 k-block (16 k) x 4 rows in its quarter.
    const int quarter = tid >> 7;                   // == wk for MMA warps
    const int qlocal = tid & 127;
    const int sblk = quarter * 8 + (qlocal >> 4);   // k-block 0..31
    const int srow0 = (qlocal & 15) * 4;            // first of 4 rows

    // Epilogue state (wk==0 threads) + staging resets (all threads).
    float2 hc[2][2];        // h carry [rr][f]
    float2 pxG[3][2][2];    // Xg [gate][rr][f]
    bool rzrow[2];
    int rstage[4];
    float2 bh2[2];
    bh2[0] = *(const float2*)&bhn[j0 + 0 + tq * 2];
    bh2[1] = *(const float2*)&bhn[j0 + 8 + tq * 2];
    {
        const int* rst = resets;    // t = 0
#pragma unroll
        for (int r4 = 0; r4 < 4; ++r4) rstage[r4] = rst[b0 + srow0 + r4];
        if (wk == 0) {
#pragma unroll
            for (int rr = 0; rr < 2; ++rr) {
                const int row = b0 + wm * 16 + g + rr * 8;
                rzrow[rr] = rst[row] != 0;
#pragma unroll
                for (int f = 0; f < 2; ++f) {
                    const int jj = j0 + f * 8 + tq * 2;
                    hc[rr][f] = *(const float2*)&init_h[(size_t)row * HH + jj];
#pragma unroll
                    for (int gate = 0; gate < 3; ++gate)
                        pxG[gate][rr][f] = *(const float2*)&g_Xg[(size_t)row * G3 + gate * 512 + jj];
                }
            }
        }
    }

    for (int t = 0; t < TT; ++t) {
        const int par = t & 1;
        const uint16_t* Hh = g_Hh + (size_t)par * BB * HH;
        const uint16_t* Hl = g_Hl + (size_t)par * BB * HH;

        // --- stage own k-quarter via cp.async with in-flight reset masking ---
#pragma unroll
        for (int r4 = 0; r4 < 4; ++r4) {
            const int row = srow0 + r4;
            const uint32_t sz = rstage[r4] ? 0u : 16u;
            const uint32_t d = (uint32_t)(sblk * 2048 + row * 32);
            const uint16_t* sh = Hh + (size_t)(b0 + row) * HH + sblk * 16;
            const uint16_t* sl = Hl + (size_t)(b0 + row) * HH + sblk * 16;
            cp16z(smb + SKB_AH + d,      sh,     sz);
            cp16z(smb + SKB_AH + d + 16, sh + 8, sz);
            cp16z(smb + SKB_AL + d,      sl,     sz);
            cp16z(smb + SKB_AL + d + 16, sl + 8, sz);
        }
        CP_COMMIT();
        CP_WAIT0();
        asm volatile("bar.sync %0, 128;" :: "r"(quarter + 1) : "memory");

        // --- MMA on own k-quarter: warp (wm, wk), c[6 n-frags][4] ---
        float c[6][4];
#pragma unroll
        for (int ni = 0; ni < 6; ++ni)
#pragma unroll
            for (int q = 0; q < 4; ++q) c[ni][q] = 0.0f;

#pragma unroll
        for (int ki = 0; ki < 8; ++ki) {
            const int blk = wk * 8 + ki;
            uint32_t afh[4], afl[4];
            const uint32_t aoff = (uint32_t)(blk * 2048 + (wm * 16 + (l & 15)) * 32 + (l >> 4) * 16);
            ldm_x4(afh, smb + SKB_AH + aoff);
            ldm_x4(afl, smb + SKB_AL + aoff);
#pragma unroll
            for (int ni = 0; ni < 6; ++ni) {
                const uint32_t woff = (uint32_t)(blk * 1536 + (ni * 8 + (l & 7)) * 32 + ((l >> 3) & 1) * 16);
                uint32_t bfh[2], bfl[2];
                ldm_x2(bfh, smb + SKB_WH + woff);
                ldm_x2(bfl, smb + SKB_WL + woff);
                mma16816(c[ni], afh, bfh);
                mma16816(c[ni], afh, bfl);
                mma16816(c[ni], afl, bfh);
            }
        }
        __syncthreads();   // all MMA smem reads done; A region reusable

        // --- 4-way k reduction via smem (layout [24][384] floats, conflict-free) ---
        if (wk != 0) {
            float* dst = red_buf + (wk - 1) * 128 + wm * 32 + l;
#pragma unroll
            for (int ni = 0; ni < 6; ++ni)
#pragma unroll
                for (int q = 0; q < 4; ++q)
                    dst[(ni * 4 + q) * 384] = c[ni][q];
        }
        __syncthreads();

        if (wk == 0) {
            const float* src = red_buf + wm * 32 + l;
#pragma unroll
            for (int ni = 0; ni < 6; ++ni)
#pragma unroll
                for (int q = 0; q < 4; ++q) {
                    const float* s = src + (ni * 4 + q) * 384;
                    c[ni][q] += s[0] + s[128] + s[256];
                }

            // --- fused GRU epilogue, register h-carry ---
            float* outt = out + (size_t)t * BB * HH;
            uint16_t* nHh = g_Hh + (size_t)(par ^ 1) * BB * HH;
            uint16_t* nHl = g_Hl + (size_t)(par ^ 1) * BB * HH;
#pragma unroll
            for (int rr = 0; rr < 2; ++rr) {
                const int row = b0 + wm * 16 + g + rr * 8;
#pragma unroll
                for (int f = 0; f < 2; ++f) {
                    const int jj = j0 + f * 8 + tq * 2;
                    float2 hp = hc[rr][f];
                    if (rzrow[rr]) { hp.x = 0.0f; hp.y = 0.0f; }
                    const float r0 = sigmoidf_(pxG[0][rr][f].x + c[0 + f][rr * 2 + 0]);
                    const float r1 = sigmoidf_(pxG[0][rr][f].y + c[0 + f][rr * 2 + 1]);
                    const float z0 = sigmoidf_(pxG[1][rr][f].x + c[2 + f][rr * 2 + 0]);
                    const float z1 = sigmoidf_(pxG[1][rr][f].y + c[2 + f][rr * 2 + 1]);
                    const float n0 = tanhf(pxG[2][rr][f].x + r0 * (c[4 + f][rr * 2 + 0] + bh2[f].x));
                    const float n1 = tanhf(pxG[2][rr][f].y + r1 * (c[4 + f][rr * 2 + 1] + bh2[f].y));
                    const float h0 = (1.0f - z0) * n0 + z0 * hp.x;
                    const float h1 = (1.0f - z1) * n1 + z1 * hp.y;
                    *(float2*)&outt[(size_t)row * HH + jj] = make_float2(h0, h1);
                    hc[rr][f] = make_float2(h0, h1);
                    uint16_t hh0, hl0, hh1, hl1;
                    split2(h0, hh0, hl0);
                    split2(h1, hh1, hl1);
                    *(uint32_t*)&nHh[(size_t)row * HH + jj] = ((uint32_t)hh1 << 16) | hh0;
                    *(uint32_t*)&nHl[(size_t)row * HH + jj] = ((uint32_t)hl1 << 16) | hl0;
                }
            }
        }

        // --- prefetch t+1 operands independent of h (hidden by the barrier) ---
        if (t + 1 < TT) {
            const int* rstn = resets + (t + 1) * BB;
#pragma unroll
            for (int r4 = 0; r4 < 4; ++r4) rstage[r4] = rstn[b0 + srow0 + r4];
            if (wk == 0) {
                const float* xgb = g_Xg + (size_t)(t + 1) * BB * G3;
#pragma unroll
                for (int rr = 0; rr < 2; ++rr) {
                    const int row = b0 + wm * 16 + g + rr * 8;
                    rzrow[rr] = rstn[row] != 0;
#pragma unroll
                    for (int f = 0; f < 2; ++f) {
                        const int jj = j0 + f * 8 + tq * 2;
#pragma unroll
                        for (int gate = 0; gate < 3; ++gate)
                            pxG[gate][rr][f] = *(const float2*)&xgb[(size_t)row * G3 + gate * 512 + jj];
                    }
                }
            }
        }

        // --- per-b-quarter barrier (32 CTAs sharing blockIdx.y) ---
        __threadfence();
        __syncthreads();
        if (tid == 0) {
            asm volatile("red.release.gpu.add.u32 [%0], %1;" :: "l"(my_bar), "r"(1u) : "memory");
            const unsigned target = 32u * (unsigned)(t + 1);
            unsigned v;
            do {
                asm volatile("ld.acquire.gpu.u32 %0, [%1];" : "=r"(v) : "l"(my_bar) : "memory");
                if (v >= target) break;
                __nanosleep(32);
            } while (true);
        }
        __syncthreads();
    }
}

// ----------------------------------------------------------------------------
// Launch: 3 prep kernels + mma input GEMM + ONE persistent recurrence kernel.
// Graph-capturable (kernel launches only), allocation-free.
// ----------------------------------------------------------------------------
extern "C" void kernel_launch(void* const* d_in, const int* in_sizes, int n_in,
                              void* d_out, int out_size)
{
    const float* ins    = (const float*)d_in[0];
    const int*   resets = (const int*)d_in[1];
    const float* init_h = (const float*)d_in[2];
    const float* W_ir   = (const float*)d_in[3];
    const float* W_iz   = (const float*)d_in[4];
    const float* W_in   = (const float*)d_in[5];
    const float* b_ir   = (const float*)d_in[6];
    const float* b_iz   = (const float*)d_in[7];
    const float* b_in   = (const float*)d_in[8];
    const float* W_hr   = (const float*)d_in[9];
    const float* W_hz   = (const float*)d_in[10];
    const float* W_hn   = (const float*)d_in[11];
    const float* b_hn   = (const float*)d_in[12];
    float* out = (float*)d_out;

    cudaFuncSetAttribute(input_gemm_mma,
                         cudaFuncAttributeMaxDynamicSharedMemorySize, IG_SMEM_BYTES);
    cudaFuncSetAttribute(gru_persistent,
                         cudaFuncAttributeMaxDynamicSharedMemorySize, SKB_TOTAL);

    prep_x_kernel<<<(int)(((size_t)MTOT * HH / 8 + 255) / 256), 256>>>(ins);
    prep_w_kernel<<<(G3 * HH / 8 + 255) / 256, 256>>>(W_ir, W_iz, W_in,
                                                      W_hr, W_hz, W_hn,
                                                      b_ir, b_iz, b_in);
    prep_h_kernel<<<(BB * HH / 8 + 255) / 256, 256>>>(init_h);

    input_gemm_mma<<<dim3(G3 / 128, MTOT / 128), 512, IG_SMEM_BYTES>>>();

    gru_persistent<<<dim3(32, 4), 512, SKB_TOTAL>>>(resets, init_h, b_hn, out);
}